// round 14
// baseline (speedup 1.0000x reference)
#include <cuda_runtime.h>
#include <cuda_bf16.h>
#include <math.h>
#include <stdint.h>

#define B_   8
#define HW_  4096
#define C_   256
#define NT_  (B_ * HW_)

static __device__ unsigned short g_hh[(size_t)NT_ * C_];
static __device__ unsigned short g_hl[(size_t)NT_ * C_];
static __device__ unsigned short g_qh[(size_t)NT_ * C_];
static __device__ unsigned short g_ql[(size_t)NT_ * C_];
static __device__ unsigned short g_kh[(size_t)NT_ * C_];
static __device__ unsigned short g_kl[(size_t)NT_ * C_];
static __device__ unsigned short g_vh[(size_t)NT_ * C_];
static __device__ unsigned short g_vl[(size_t)NT_ * C_];
static __device__ unsigned short g_aoh[(size_t)NT_ * C_];
static __device__ unsigned short g_aol[(size_t)NT_ * C_];
static __device__ unsigned short g_wh[4][C_ * C_];
static __device__ unsigned short g_wl[4][C_ * C_];

// ---------------- helpers (sm_80-level PTX only) ----------------
__device__ __forceinline__ uint32_t smem_u32(const void* p) {
    uint32_t a;
    asm("{ .reg .u64 t; cvta.to.shared.u64 t, %1; cvt.u32.u64 %0, t; }" : "=r"(a) : "l"(p));
    return a;
}
__device__ __forceinline__ void cpa16(uint32_t s, const void* g) {
    asm volatile("cp.async.cg.shared.global [%0], [%1], 16;" :: "r"(s), "l"(g));
}
#define CP_COMMIT() asm volatile("cp.async.commit_group;" ::: "memory")
#define CP_WAIT0()  asm volatile("cp.async.wait_group 0;" ::: "memory")
#define CP_WAIT1()  asm volatile("cp.async.wait_group 1;" ::: "memory")
#define LDSM4(R, A) \
    asm volatile("ldmatrix.sync.aligned.m8n8.x4.shared.b16 {%0,%1,%2,%3}, [%4];" \
        : "=r"((R)[0]), "=r"((R)[1]), "=r"((R)[2]), "=r"((R)[3]) : "r"(A))
#define LDSM4T(R, A) \
    asm volatile("ldmatrix.sync.aligned.m8n8.x4.trans.shared.b16 {%0,%1,%2,%3}, [%4];" \
        : "=r"((R)[0]), "=r"((R)[1]), "=r"((R)[2]), "=r"((R)[3]) : "r"(A))
__device__ __forceinline__ void mma16816(float* c, const uint32_t* a, uint32_t b0, uint32_t b1) {
    asm volatile("mma.sync.aligned.m16n8k16.row.col.f32.bf16.bf16.f32 "
                 "{%0,%1,%2,%3}, {%4,%5,%6,%7}, {%8,%9}, {%0,%1,%2,%3};"
                 : "+f"(c[0]), "+f"(c[1]), "+f"(c[2]), "+f"(c[3])
                 : "r"(a[0]), "r"(a[1]), "r"(a[2]), "r"(a[3]), "r"(b0), "r"(b1));
}
__device__ __forceinline__ uint32_t pack2(__nv_bfloat16 a, __nv_bfloat16 b) {
    __nv_bfloat162 t; t.x = a; t.y = b;
    return *reinterpret_cast<uint32_t*>(&t);
}
__device__ __forceinline__ void split2(float f, __nv_bfloat16& h, __nv_bfloat16& l) {
    h = __float2bfloat16(f);
    l = __float2bfloat16(f - __bfloat162float(h));
}
__device__ __forceinline__ uint32_t packhi(float a, float b) {
    return pack2(__float2bfloat16(a), __float2bfloat16(b));
}
__device__ __forceinline__ uint32_t packlo(float a, float b) {
    __nv_bfloat16 ha = __float2bfloat16(a), hb = __float2bfloat16(b);
    return pack2(__float2bfloat16(a - __bfloat162float(ha)),
                 __float2bfloat16(b - __bfloat162float(hb)));
}

// ---------------- LayerNorm -> bf16 hi/lo ----------------
__global__ __launch_bounds__(256) void ln_kernel(
    const float* __restrict__ x, const float* __restrict__ gamma,
    const float* __restrict__ beta,
    unsigned short* __restrict__ hh, unsigned short* __restrict__ hl)
{
    int token = blockIdx.x * 8 + (threadIdx.x >> 5);
    int lane  = threadIdx.x & 31;
    const float4* xr = (const float4*)(x + (size_t)token * C_);
    float4 a = xr[lane];
    float4 b = xr[lane + 32];
    float s  = a.x + a.y + a.z + a.w + b.x + b.y + b.z + b.w;
    float s2 = a.x*a.x + a.y*a.y + a.z*a.z + a.w*a.w
             + b.x*b.x + b.y*b.y + b.z*b.z + b.w*b.w;
#pragma unroll
    for (int o = 16; o; o >>= 1) {
        s  += __shfl_xor_sync(0xffffffffu, s,  o);
        s2 += __shfl_xor_sync(0xffffffffu, s2, o);
    }
    float mu   = s * (1.0f / C_);
    float rstd = rsqrtf(s2 * (1.0f / C_) - mu * mu + 1e-5f);
    float4 g0 = ((const float4*)gamma)[lane], g1 = ((const float4*)gamma)[lane + 32];
    float4 e0 = ((const float4*)beta)[lane],  e1 = ((const float4*)beta)[lane + 32];
    float o0[4], o1[4];
    o0[0] = (a.x-mu)*rstd*g0.x + e0.x; o0[1] = (a.y-mu)*rstd*g0.y + e0.y;
    o0[2] = (a.z-mu)*rstd*g0.z + e0.z; o0[3] = (a.w-mu)*rstd*g0.w + e0.w;
    o1[0] = (b.x-mu)*rstd*g1.x + e1.x; o1[1] = (b.y-mu)*rstd*g1.y + e1.y;
    o1[2] = (b.z-mu)*rstd*g1.z + e1.z; o1[3] = (b.w-mu)*rstd*g1.w + e1.w;
    uint2 h0, l0, h1, l1;
    h0.x = packhi(o0[0],o0[1]); h0.y = packhi(o0[2],o0[3]);
    l0.x = packlo(o0[0],o0[1]); l0.y = packlo(o0[2],o0[3]);
    h1.x = packhi(o1[0],o1[1]); h1.y = packhi(o1[2],o1[3]);
    l1.x = packlo(o1[0],o1[1]); l1.y = packlo(o1[2],o1[3]);
    ((uint2*)(hh + (size_t)token * C_))[lane]      = h0;
    ((uint2*)(hh + (size_t)token * C_))[lane + 32] = h1;
    ((uint2*)(hl + (size_t)token * C_))[lane]      = l0;
    ((uint2*)(hl + (size_t)token * C_))[lane + 32] = l1;
}

// ---------------- fp32 -> bf16 hi/lo split (weights) ----------------
__global__ __launch_bounds__(256) void cvt_split_kernel(
    const float* __restrict__ in, unsigned short* __restrict__ hi,
    unsigned short* __restrict__ lo)
{
    size_t i = ((size_t)blockIdx.x * 256 + threadIdx.x) * 4;
    float4 v = *(const float4*)(in + i);
    uint2 hv, lv;
    hv.x = packhi(v.x, v.y); hv.y = packhi(v.z, v.w);
    lv.x = packlo(v.x, v.y); lv.y = packlo(v.z, v.w);
    *(uint2*)(hi + i) = hv;
    *(uint2*)(lo + i) = lv;
}

// ---------------- bf16-input double-buffered mma.sync GEMM ----------------
// out[M,256] = (Ahi+Alo)@(Whi+Wlo) 3-term + bias (+resid)
// Stage: AH@0(10240) AL@10240 WH@20480(8704) WL@29184 ; stride 37888; 2 stages.
#define G2_STG 37888

__device__ __forceinline__ void g2_fill(
    uint32_t d, const unsigned short* Ah, const unsigned short* Al,
    const unsigned short* Wh, const unsigned short* Wl,
    int m0, int n0, int k0, int tid)
{
#pragma unroll
    for (int r = 0; r < 2; ++r) {
        int c = tid + r * 256;
        int m = c >> 2, kq = c & 3;
        cpa16(d + m*80 + kq*16,          Ah + (size_t)(m0+m)*C_ + k0 + kq*8);
        cpa16(d + 10240u + m*80 + kq*16, Al + (size_t)(m0+m)*C_ + k0 + kq*8);
    }
#pragma unroll
    for (int r = 0; r < 2; ++r) {
        int c = tid + r * 256;
        int k = c >> 4, nq = c & 15;
        cpa16(d + 20480u + k*272 + nq*16, Wh + (size_t)(k0+k)*C_ + n0 + nq*8);
        cpa16(d + 29184u + k*272 + nq*16, Wl + (size_t)(k0+k)*C_ + n0 + nq*8);
    }
}

__global__ __launch_bounds__(256) void gemm2_kernel(
    const unsigned short* __restrict__ Ah, const unsigned short* __restrict__ Al,
    const unsigned short* __restrict__ Wh, const unsigned short* __restrict__ Wl,
    const float* __restrict__ bias, const float* __restrict__ resid,
    float* __restrict__ outf,
    unsigned short* __restrict__ ohi, unsigned short* __restrict__ olo)
{
    __shared__ char gsm[2 * G2_STG];
    const uint32_t sb = smem_u32(gsm);
    const int tid = threadIdx.x, lane = tid & 31, w = tid >> 5;
    const int wm = w & 3, wn = w >> 2;
    const int m0 = blockIdx.y * 128, n0 = blockIdx.x * 128;
    const int t8 = lane & 7, gq = lane >> 3;

    float acc[2][8][4];
#pragma unroll
    for (int i = 0; i < 2; ++i)
#pragma unroll
        for (int j = 0; j < 8; ++j)
#pragma unroll
            for (int q = 0; q < 4; ++q) acc[i][j][q] = 0.f;

    g2_fill(sb,          Ah, Al, Wh, Wl, m0, n0, 0,  tid); CP_COMMIT();
    g2_fill(sb + G2_STG, Ah, Al, Wh, Wl, m0, n0, 32, tid); CP_COMMIT();

    for (int s = 0; s < 8; ++s) {
        if (s < 7) { CP_WAIT1(); } else { CP_WAIT0(); }
        __syncthreads();
        const uint32_t base = sb + (uint32_t)((s & 1) * G2_STG);
#pragma unroll
        for (int kk = 0; kk < 2; ++kk) {
            uint32_t ah[2][4], al[2][4];
#pragma unroll
            for (int mt = 0; mt < 2; ++mt) {
                int row = wm*32 + mt*16 + ((gq&1)<<3) + t8;
                uint32_t ad = base + row*80 + kk*32 + (gq>>1)*16;
                LDSM4(ah[mt], ad);
                LDSM4(al[mt], ad + 10240u);
            }
            int rowk = kk*16 + ((gq&1)<<3) + t8;
#pragma unroll
            for (int j = 0; j < 4; ++j) {
                uint32_t bd = base + 20480u + rowk*272 + wn*128 + (2*j + (gq>>1))*16;
                uint32_t bh[4], bl[4];
                LDSM4T(bh, bd);
                LDSM4T(bl, bd + 8704u);
#pragma unroll
                for (int mt = 0; mt < 2; ++mt) {
                    mma16816(acc[mt][2*j],   ah[mt], bh[0], bh[1]);
                    mma16816(acc[mt][2*j],   ah[mt], bl[0], bl[1]);
                    mma16816(acc[mt][2*j],   al[mt], bh[0], bh[1]);
                    mma16816(acc[mt][2*j+1], ah[mt], bh[2], bh[3]);
                    mma16816(acc[mt][2*j+1], ah[mt], bl[2], bl[3]);
                    mma16816(acc[mt][2*j+1], al[mt], bh[2], bh[3]);
                }
            }
        }
        __syncthreads();
        if (s < 6) {
            g2_fill(sb + (uint32_t)((s & 1) * G2_STG),
                    Ah, Al, Wh, Wl, m0, n0, (s + 2) * 32, tid);
            CP_COMMIT();
        }
    }

#pragma unroll
    for (int mt = 0; mt < 2; ++mt)
#pragma unroll
        for (int n8 = 0; n8 < 8; ++n8) {
            int row = m0 + wm*32 + mt*16 + (lane >> 2);
            int col = n0 + wn*64 + n8*8 + (lane & 3)*2;
            size_t o0 = (size_t)row * C_ + col, o1 = o0 + 8 * C_;
            float b0 = bias[col], b1 = bias[col + 1];
            float v00 = acc[mt][n8][0] + b0, v01 = acc[mt][n8][1] + b1;
            float v10 = acc[mt][n8][2] + b0, v11 = acc[mt][n8][3] + b1;
            if (resid) {
                v00 += resid[o0]; v01 += resid[o0 + 1];
                v10 += resid[o1]; v11 += resid[o1 + 1];
            }
            if (outf) {
                *(float2*)(outf + o0) = make_float2(v00, v01);
                *(float2*)(outf + o1) = make_float2(v10, v11);
            }
            if (ohi) {
                *(uint32_t*)(ohi + o0) = packhi(v00, v01);
                *(uint32_t*)(olo + o0) = packlo(v00, v01);
                *(uint32_t*)(ohi + o1) = packhi(v10, v11);
                *(uint32_t*)(olo + o1) = packlo(v10, v11);
            }
        }
}

// ---------------- mma.sync flash attention (R10 structure, BN=64) ----------
// SMEM: Qhi 64K | Qlo 64K | KV hi 32K + lo 32K = 192K
#define SM_QH 0
#define SM_QL 65536
#define SM_KH 131072
#define ATTN_SMEM (131072 + 65536)

__global__ __launch_bounds__(256, 1) void attn_mma_kernel(
    const unsigned short* __restrict__ QH, const unsigned short* __restrict__ QL,
    const unsigned short* __restrict__ KH, const unsigned short* __restrict__ KL,
    const unsigned short* __restrict__ VH, const unsigned short* __restrict__ VL,
    unsigned short* __restrict__ OH, unsigned short* __restrict__ OL)
{
    extern __shared__ char smc[];
    const uint32_t sb = smem_u32(smc);
    const int tid = threadIdx.x, lane = tid & 31, w = tid >> 5;
    const int b = blockIdx.y, m0 = blockIdx.x * 128;

    // Q hi/lo -> swizzled smem via cp.async (group 0)
    {
        const unsigned short* QHb = QH + ((size_t)b * HW_ + m0) * C_;
        const unsigned short* QLb = QL + ((size_t)b * HW_ + m0) * C_;
        for (int u = tid; u < 4096; u += 256) {
            int row = u >> 5, cc = u & 31;
            uint32_t sw = (uint32_t)(row * 512 + ((cc ^ (row & 7)) << 4));
            cpa16(sb + SM_QH + sw, QHb + (size_t)row * C_ + cc * 8);
            cpa16(sb + SM_QL + sw, QLb + (size_t)row * C_ + cc * 8);
        }
        CP_COMMIT();
    }

    const int t8 = lane & 7, gq = lane >> 3;
    const int arow  = (w << 4) + ((gq & 1) << 3) + t8;
    const uint32_t aoff = sb + SM_QH + arow * 512;
    const int arow7 = arow & 7, akh = gq >> 1;
    const int brow_l = ((gq >> 1) << 3) + t8, bkh = gq & 1;
    const int vrow_l = ((gq & 1) << 3) + t8, vnh = gq >> 1;

    float oacc[128];
#pragma unroll
    for (int i = 0; i < 128; ++i) oacc[i] = 0.f;
    float l0 = 0.f, l1 = 0.f;

    const unsigned short* KHb = KH + (size_t)b * HW_ * C_;
    const unsigned short* KLb = KL + (size_t)b * HW_ * C_;
    const unsigned short* VHb = VH + (size_t)b * HW_ * C_;
    const unsigned short* VLb = VL + (size_t)b * HW_ * C_;

    for (int kt = 0; kt < 64; ++kt) {
        __syncthreads();                       // prev V readers done
        {   // K tile 64x256 hi/lo -> smem
            size_t base = (size_t)kt * 64 * C_;
#pragma unroll
            for (int rq = 0; rq < 8; ++rq) {
                int u = tid + rq * 256;
                int row = u >> 5, cc = u & 31;
                uint32_t sw = (uint32_t)(row * 512 + ((cc ^ (row & 7)) << 4));
                cpa16(sb + SM_KH + sw,          KHb + base + row * C_ + cc * 8);
                cpa16(sb + SM_KH + 32768u + sw, KLb + base + row * C_ + cc * 8);
            }
            CP_COMMIT(); CP_WAIT0();           // also retires Q on iter 0
        }
        __syncthreads();

        // ---- S = Q K^T ----
        float sacc[32];
#pragma unroll
        for (int i = 0; i < 32; ++i) sacc[i] = 0.f;
#pragma unroll 2
        for (int kk = 0; kk < 16; ++kk) {
            uint32_t ah[4], al[4];
            uint32_t ad = aoff + (uint32_t)(((2*kk + akh) ^ arow7) << 4);
            LDSM4(ah, ad);
            LDSM4(al, ad + 65536u);
#pragma unroll
            for (int np = 0; np < 4; ++np) {
                int brow = np * 16 + brow_l;
                uint32_t bd = sb + SM_KH +
                    (uint32_t)(brow * 512 + (((2*kk + bkh) ^ (brow & 7)) << 4));
                uint32_t bh[4], bl[4];
                LDSM4(bh, bd);
                LDSM4(bl, bd + 32768u);
                mma16816(&sacc[(2*np)*4],   ah, bh[0], bh[1]);
                mma16816(&sacc[(2*np)*4],   ah, bl[0], bl[1]);
                mma16816(&sacc[(2*np)*4],   al, bh[0], bh[1]);
                mma16816(&sacc[(2*np+1)*4], ah, bh[2], bh[3]);
                mma16816(&sacc[(2*np+1)*4], ah, bl[2], bl[3]);
                mma16816(&sacc[(2*np+1)*4], al, bh[2], bh[3]);
            }
        }

        __syncthreads();                       // all warps done reading K
        {   // V tile -> same buffer, overlapped with softmax
            size_t base = (size_t)kt * 64 * C_;
#pragma unroll
            for (int rq = 0; rq < 8; ++rq) {
                int u = tid + rq * 256;
                int row = u >> 5, cc = u & 31;
                uint32_t sw = (uint32_t)(row * 512 + ((cc ^ (row & 7)) << 4));
                cpa16(sb + SM_KH + sw,          VHb + base + row * C_ + cc * 8);
                cpa16(sb + SM_KH + 32768u + sw, VLb + base + row * C_ + cc * 8);
            }
            CP_COMMIT();
        }

        // ---- softmax (bounded logits: no max-sub; 1/16 folded here) ----
        uint32_t ph[4][4], pl[4][4];
#pragma unroll
        for (int j = 0; j < 4; ++j) {
            float e[8];
#pragma unroll
            for (int i = 0; i < 4; ++i) {
                e[i]   = __expf(sacc[(2*j)*4 + i]   * 0.0625f);
                e[4+i] = __expf(sacc[(2*j+1)*4 + i] * 0.0625f);
            }
            l0 += e[0] + e[1] + e[4] + e[5];
            l1 += e[2] + e[3] + e[6] + e[7];
            ph[j][0] = packhi(e[0], e[1]); pl[j][0] = packlo(e[0], e[1]);
            ph[j][1] = packhi(e[2], e[3]); pl[j][1] = packlo(e[2], e[3]);
            ph[j][2] = packhi(e[4], e[5]); pl[j][2] = packlo(e[4], e[5]);
            ph[j][3] = packhi(e[6], e[7]); pl[j][3] = packlo(e[6], e[7]);
        }

        CP_WAIT0();
        __syncthreads();

        // ---- O += P V ----
#pragma unroll
        for (int j = 0; j < 4; ++j) {
            int vrow = j * 16 + vrow_l;
            uint32_t vbase = sb + SM_KH + (uint32_t)(vrow * 512);
            int vrow7 = vrow & 7;
#pragma unroll
            for (int p = 0; p < 16; ++p) {
                uint32_t vd = vbase + (uint32_t)(((2*p + vnh) ^ vrow7) << 4);
                uint32_t bh[4], bl[4];
                LDSM4T(bh, vd);
                LDSM4T(bl, vd + 32768u);
                mma16816(&oacc[(2*p)*4],   ph[j], bh[0], bh[1]);
                mma16816(&oacc[(2*p)*4],   ph[j], bl[0], bl[1]);
                mma16816(&oacc[(2*p)*4],   pl[j], bh[0], bh[1]);
                mma16816(&oacc[(2*p+1)*4], ph[j], bh[2], bh[3]);
                mma16816(&oacc[(2*p+1)*4], ph[j], bl[2], bl[3]);
                mma16816(&oacc[(2*p+1)*4], pl[j], bh[2], bh[3]);
            }
        }
    }

    // ---- epilogue: O /= l, store as bf16 hi/lo split ----
    l0 += __shfl_xor_sync(0xffffffffu, l0, 1);
    l0 += __shfl_xor_sync(0xffffffffu, l0, 2);
    l1 += __shfl_xor_sync(0xffffffffu, l1, 1);
    l1 += __shfl_xor_sync(0xffffffffu, l1, 2);
    float i0 = 1.f / l0, i1 = 1.f / l1;
    int r = lane >> 2, cq = (lane & 3) * 2;
    size_t ob = ((size_t)b * HW_ + m0 + w * 16) * C_;
#pragma unroll
    for (int nn = 0; nn < 32; ++nn) {
        float a0 = oacc[nn*4]   * i0, a1 = oacc[nn*4+1] * i0;
        float b0 = oacc[nn*4+2] * i1, b1 = oacc[nn*4+3] * i1;
        size_t p0 = ob + (size_t)r * C_ + nn * 8 + cq;
        size_t p1 = ob + (size_t)(r + 8) * C_ + nn * 8 + cq;
        *(uint32_t*)(OH + p0) = packhi(a0, a1);
        *(uint32_t*)(OL + p0) = packlo(a0, a1);
        *(uint32_t*)(OH + p1) = packhi(b0, b1);
        *(uint32_t*)(OL + p1) = packlo(b0, b1);
    }
}

// ---------------- launch ----------------
extern "C" void kernel_launch(void* const* d_in, const int* in_sizes, int n_in,
                              void* d_out, int out_size)
{
    const float* x   = (const float*)d_in[0];
    const float* gam = (const float*)d_in[1];
    const float* bet = (const float*)d_in[2];
    const float* wq  = (const float*)d_in[3];
    const float* bq  = (const float*)d_in[4];
    const float* wk  = (const float*)d_in[5];
    const float* bk  = (const float*)d_in[6];
    const float* wv  = (const float*)d_in[7];
    const float* bv  = (const float*)d_in[8];
    const float* wo  = (const float*)d_in[9];
    const float* bo  = (const float*)d_in[10];
    float* out = (float*)d_out;

    unsigned short *hh, *hl, *qh, *ql, *kh, *kl, *vh, *vl, *aoh, *aol, *wsh, *wsl;
    cudaGetSymbolAddress((void**)&hh,  g_hh);
    cudaGetSymbolAddress((void**)&hl,  g_hl);
    cudaGetSymbolAddress((void**)&qh,  g_qh);
    cudaGetSymbolAddress((void**)&ql,  g_ql);
    cudaGetSymbolAddress((void**)&kh,  g_kh);
    cudaGetSymbolAddress((void**)&kl,  g_kl);
    cudaGetSymbolAddress((void**)&vh,  g_vh);
    cudaGetSymbolAddress((void**)&vl,  g_vl);
    cudaGetSymbolAddress((void**)&aoh, g_aoh);
    cudaGetSymbolAddress((void**)&aol, g_aol);
    cudaGetSymbolAddress((void**)&wsh, g_wh);
    cudaGetSymbolAddress((void**)&wsl, g_wl);

    cudaFuncSetAttribute(attn_mma_kernel,
                         cudaFuncAttributeMaxDynamicSharedMemorySize, ATTN_SMEM);

    ln_kernel<<<NT_ / 8, 256>>>(x, gam, bet, hh, hl);

    const int WG = (C_ * C_) / (256 * 4);   // 64 blocks per weight
    cvt_split_kernel<<<WG, 256>>>(wq, wsh + 0*C_*C_, wsl + 0*C_*C_);
    cvt_split_kernel<<<WG, 256>>>(wk, wsh + 1*C_*C_, wsl + 1*C_*C_);
    cvt_split_kernel<<<WG, 256>>>(wv, wsh + 2*C_*C_, wsl + 2*C_*C_);
    cvt_split_kernel<<<WG, 256>>>(wo, wsh + 3*C_*C_, wsl + 3*C_*C_);

    dim3 gg(C_ / 128, NT_ / 128);   // (2, 256)
    gemm2_kernel<<<gg, 256>>>(hh, hl, wsh + 0*C_*C_, wsl + 0*C_*C_, bq, nullptr,
                              nullptr, qh, ql);
    gemm2_kernel<<<gg, 256>>>(hh, hl, wsh + 1*C_*C_, wsl + 1*C_*C_, bk, nullptr,
                              nullptr, kh, kl);
    gemm2_kernel<<<gg, 256>>>(hh, hl, wsh + 2*C_*C_, wsl + 2*C_*C_, bv, nullptr,
                              nullptr, vh, vl);

    attn_mma_kernel<<<dim3(HW_ / 128, B_), 256, ATTN_SMEM>>>(qh, ql, kh, kl, vh, vl, aoh, aol);

    gemm2_kernel<<<gg, 256>>>(aoh, aol, wsh + 3*C_*C_, wsl + 3*C_*C_, bo, x,
                              out, nullptr, nullptr);
}

// round 15
// speedup vs baseline: 1.0009x; 1.0009x over previous
#include <cuda_runtime.h>
#include <cuda_bf16.h>
#include <math.h>
#include <stdint.h>

#define B_   8
#define HW_  4096
#define C_   256
#define NT_  (B_ * HW_)

static __device__ unsigned short g_hh[(size_t)NT_ * C_];
static __device__ unsigned short g_hl[(size_t)NT_ * C_];
static __device__ unsigned short g_qh[(size_t)NT_ * C_];
static __device__ unsigned short g_ql[(size_t)NT_ * C_];
static __device__ unsigned short g_kh[(size_t)NT_ * C_];
static __device__ unsigned short g_kl[(size_t)NT_ * C_];
static __device__ unsigned short g_vh[(size_t)NT_ * C_];
static __device__ unsigned short g_vl[(size_t)NT_ * C_];
static __device__ unsigned short g_aoh[(size_t)NT_ * C_];
static __device__ unsigned short g_aol[(size_t)NT_ * C_];
static __device__ unsigned short g_wh[4][C_ * C_];
static __device__ unsigned short g_wl[4][C_ * C_];

// ---------------- helpers (sm_80-level PTX only) ----------------
__device__ __forceinline__ uint32_t smem_u32(const void* p) {
    uint32_t a;
    asm("{ .reg .u64 t; cvta.to.shared.u64 t, %1; cvt.u32.u64 %0, t; }" : "=r"(a) : "l"(p));
    return a;
}
__device__ __forceinline__ void cpa16(uint32_t s, const void* g) {
    asm volatile("cp.async.cg.shared.global [%0], [%1], 16;" :: "r"(s), "l"(g));
}
#define CP_COMMIT() asm volatile("cp.async.commit_group;" ::: "memory")
#define CP_WAIT0()  asm volatile("cp.async.wait_group 0;" ::: "memory")
#define CP_WAIT1()  asm volatile("cp.async.wait_group 1;" ::: "memory")
#define LDSM4(R, A) \
    asm volatile("ldmatrix.sync.aligned.m8n8.x4.shared.b16 {%0,%1,%2,%3}, [%4];" \
        : "=r"((R)[0]), "=r"((R)[1]), "=r"((R)[2]), "=r"((R)[3]) : "r"(A))
#define LDSM4T(R, A) \
    asm volatile("ldmatrix.sync.aligned.m8n8.x4.trans.shared.b16 {%0,%1,%2,%3}, [%4];" \
        : "=r"((R)[0]), "=r"((R)[1]), "=r"((R)[2]), "=r"((R)[3]) : "r"(A))
__device__ __forceinline__ void mma16816(float* c, const uint32_t* a, uint32_t b0, uint32_t b1) {
    asm volatile("mma.sync.aligned.m16n8k16.row.col.f32.bf16.bf16.f32 "
                 "{%0,%1,%2,%3}, {%4,%5,%6,%7}, {%8,%9}, {%0,%1,%2,%3};"
                 : "+f"(c[0]), "+f"(c[1]), "+f"(c[2]), "+f"(c[3])
                 : "r"(a[0]), "r"(a[1]), "r"(a[2]), "r"(a[3]), "r"(b0), "r"(b1));
}
__device__ __forceinline__ uint32_t pack2(__nv_bfloat16 a, __nv_bfloat16 b) {
    __nv_bfloat162 t; t.x = a; t.y = b;
    return *reinterpret_cast<uint32_t*>(&t);
}
__device__ __forceinline__ void split2(float f, __nv_bfloat16& h, __nv_bfloat16& l) {
    h = __float2bfloat16(f);
    l = __float2bfloat16(f - __bfloat162float(h));
}
__device__ __forceinline__ uint32_t packhi(float a, float b) {
    return pack2(__float2bfloat16(a), __float2bfloat16(b));
}
__device__ __forceinline__ uint32_t packlo(float a, float b) {
    __nv_bfloat16 ha = __float2bfloat16(a), hb = __float2bfloat16(b);
    return pack2(__float2bfloat16(a - __bfloat162float(ha)),
                 __float2bfloat16(b - __bfloat162float(hb)));
}

// ---------------- LayerNorm -> bf16 hi/lo ----------------
__global__ __launch_bounds__(256) void ln_kernel(
    const float* __restrict__ x, const float* __restrict__ gamma,
    const float* __restrict__ beta,
    unsigned short* __restrict__ hh, unsigned short* __restrict__ hl)
{
    int token = blockIdx.x * 8 + (threadIdx.x >> 5);
    int lane  = threadIdx.x & 31;
    const float4* xr = (const float4*)(x + (size_t)token * C_);
    float4 a = xr[lane];
    float4 b = xr[lane + 32];
    float s  = a.x + a.y + a.z + a.w + b.x + b.y + b.z + b.w;
    float s2 = a.x*a.x + a.y*a.y + a.z*a.z + a.w*a.w
             + b.x*b.x + b.y*b.y + b.z*b.z + b.w*b.w;
#pragma unroll
    for (int o = 16; o; o >>= 1) {
        s  += __shfl_xor_sync(0xffffffffu, s,  o);
        s2 += __shfl_xor_sync(0xffffffffu, s2, o);
    }
    float mu   = s * (1.0f / C_);
    float rstd = rsqrtf(s2 * (1.0f / C_) - mu * mu + 1e-5f);
    float4 g0 = ((const float4*)gamma)[lane], g1 = ((const float4*)gamma)[lane + 32];
    float4 e0 = ((const float4*)beta)[lane],  e1 = ((const float4*)beta)[lane + 32];
    float o0[4], o1[4];
    o0[0] = (a.x-mu)*rstd*g0.x + e0.x; o0[1] = (a.y-mu)*rstd*g0.y + e0.y;
    o0[2] = (a.z-mu)*rstd*g0.z + e0.z; o0[3] = (a.w-mu)*rstd*g0.w + e0.w;
    o1[0] = (b.x-mu)*rstd*g1.x + e1.x; o1[1] = (b.y-mu)*rstd*g1.y + e1.y;
    o1[2] = (b.z-mu)*rstd*g1.z + e1.z; o1[3] = (b.w-mu)*rstd*g1.w + e1.w;
    uint2 h0, l0, h1, l1;
    h0.x = packhi(o0[0],o0[1]); h0.y = packhi(o0[2],o0[3]);
    l0.x = packlo(o0[0],o0[1]); l0.y = packlo(o0[2],o0[3]);
    h1.x = packhi(o1[0],o1[1]); h1.y = packhi(o1[2],o1[3]);
    l1.x = packlo(o1[0],o1[1]); l1.y = packlo(o1[2],o1[3]);
    ((uint2*)(hh + (size_t)token * C_))[lane]      = h0;
    ((uint2*)(hh + (size_t)token * C_))[lane + 32] = h1;
    ((uint2*)(hl + (size_t)token * C_))[lane]      = l0;
    ((uint2*)(hl + (size_t)token * C_))[lane + 32] = l1;
}

// ---------------- fp32 -> bf16 hi/lo split (weights) ----------------
__global__ __launch_bounds__(256) void cvt_split_kernel(
    const float* __restrict__ in, unsigned short* __restrict__ hi,
    unsigned short* __restrict__ lo)
{
    size_t i = ((size_t)blockIdx.x * 256 + threadIdx.x) * 4;
    float4 v = *(const float4*)(in + i);
    uint2 hv, lv;
    hv.x = packhi(v.x, v.y); hv.y = packhi(v.z, v.w);
    lv.x = packlo(v.x, v.y); lv.y = packlo(v.z, v.w);
    *(uint2*)(hi + i) = hv;
    *(uint2*)(lo + i) = lv;
}

// ---------------- bf16-input double-buffered mma.sync GEMM ----------------
// out[M,256] = (Ahi+Alo)@(Whi+Wlo) 3-term + bias (+resid)
// Stage: AH@0(10240) AL@10240 WH@20480(8704) WL@29184 ; stride 37888; 2 stages.
#define G2_STG 37888

__device__ __forceinline__ void g2_fill(
    uint32_t d, const unsigned short* Ah, const unsigned short* Al,
    const unsigned short* Wh, const unsigned short* Wl,
    int m0, int n0, int k0, int tid)
{
#pragma unroll
    for (int r = 0; r < 2; ++r) {
        int c = tid + r * 256;
        int m = c >> 2, kq = c & 3;
        cpa16(d + m*80 + kq*16,          Ah + (size_t)(m0+m)*C_ + k0 + kq*8);
        cpa16(d + 10240u + m*80 + kq*16, Al + (size_t)(m0+m)*C_ + k0 + kq*8);
    }
#pragma unroll
    for (int r = 0; r < 2; ++r) {
        int c = tid + r * 256;
        int k = c >> 4, nq = c & 15;
        cpa16(d + 20480u + k*272 + nq*16, Wh + (size_t)(k0+k)*C_ + n0 + nq*8);
        cpa16(d + 29184u + k*272 + nq*16, Wl + (size_t)(k0+k)*C_ + n0 + nq*8);
    }
}

__global__ __launch_bounds__(256) void gemm2_kernel(
    const unsigned short* __restrict__ Ah, const unsigned short* __restrict__ Al,
    const unsigned short* __restrict__ Wh, const unsigned short* __restrict__ Wl,
    const float* __restrict__ bias, const float* __restrict__ resid,
    float* __restrict__ outf,
    unsigned short* __restrict__ ohi, unsigned short* __restrict__ olo)
{
    __shared__ char gsm[2 * G2_STG];
    const uint32_t sb = smem_u32(gsm);
    const int tid = threadIdx.x, lane = tid & 31, w = tid >> 5;
    const int wm = w & 3, wn = w >> 2;
    const int m0 = blockIdx.y * 128, n0 = blockIdx.x * 128;
    const int t8 = lane & 7, gq = lane >> 3;

    float acc[2][8][4];
#pragma unroll
    for (int i = 0; i < 2; ++i)
#pragma unroll
        for (int j = 0; j < 8; ++j)
#pragma unroll
            for (int q = 0; q < 4; ++q) acc[i][j][q] = 0.f;

    g2_fill(sb,          Ah, Al, Wh, Wl, m0, n0, 0,  tid); CP_COMMIT();
    g2_fill(sb + G2_STG, Ah, Al, Wh, Wl, m0, n0, 32, tid); CP_COMMIT();

    for (int s = 0; s < 8; ++s) {
        if (s < 7) { CP_WAIT1(); } else { CP_WAIT0(); }
        __syncthreads();
        const uint32_t base = sb + (uint32_t)((s & 1) * G2_STG);
#pragma unroll
        for (int kk = 0; kk < 2; ++kk) {
            uint32_t ah[2][4], al[2][4];
#pragma unroll
            for (int mt = 0; mt < 2; ++mt) {
                int row = wm*32 + mt*16 + ((gq&1)<<3) + t8;
                uint32_t ad = base + row*80 + kk*32 + (gq>>1)*16;
                LDSM4(ah[mt], ad);
                LDSM4(al[mt], ad + 10240u);
            }
            int rowk = kk*16 + ((gq&1)<<3) + t8;
#pragma unroll
            for (int j = 0; j < 4; ++j) {
                uint32_t bd = base + 20480u + rowk*272 + wn*128 + (2*j + (gq>>1))*16;
                uint32_t bh[4], bl[4];
                LDSM4T(bh, bd);
                LDSM4T(bl, bd + 8704u);
#pragma unroll
                for (int mt = 0; mt < 2; ++mt) {
                    mma16816(acc[mt][2*j],   ah[mt], bh[0], bh[1]);
                    mma16816(acc[mt][2*j],   ah[mt], bl[0], bl[1]);
                    mma16816(acc[mt][2*j],   al[mt], bh[0], bh[1]);
                    mma16816(acc[mt][2*j+1], ah[mt], bh[2], bh[3]);
                    mma16816(acc[mt][2*j+1], ah[mt], bl[2], bl[3]);
                    mma16816(acc[mt][2*j+1], al[mt], bh[2], bh[3]);
                }
            }
        }
        __syncthreads();
        if (s < 6) {
            g2_fill(sb + (uint32_t)((s & 1) * G2_STG),
                    Ah, Al, Wh, Wl, m0, n0, (s + 2) * 32, tid);
            CP_COMMIT();
        }
    }

#pragma unroll
    for (int mt = 0; mt < 2; ++mt)
#pragma unroll
        for (int n8 = 0; n8 < 8; ++n8) {
            int row = m0 + wm*32 + mt*16 + (lane >> 2);
            int col = n0 + wn*64 + n8*8 + (lane & 3)*2;
            size_t o0 = (size_t)row * C_ + col, o1 = o0 + 8 * C_;
            float b0 = bias[col], b1 = bias[col + 1];
            float v00 = acc[mt][n8][0] + b0, v01 = acc[mt][n8][1] + b1;
            float v10 = acc[mt][n8][2] + b0, v11 = acc[mt][n8][3] + b1;
            if (resid) {
                v00 += resid[o0]; v01 += resid[o0 + 1];
                v10 += resid[o1]; v11 += resid[o1 + 1];
            }
            if (outf) {
                *(float2*)(outf + o0) = make_float2(v00, v01);
                *(float2*)(outf + o1) = make_float2(v10, v11);
            }
            if (ohi) {
                *(uint32_t*)(ohi + o0) = packhi(v00, v01);
                *(uint32_t*)(olo + o0) = packlo(v00, v01);
                *(uint32_t*)(ohi + o1) = packhi(v10, v11);
                *(uint32_t*)(olo + o1) = packlo(v10, v11);
            }
        }
}

// ---------------- mma.sync flash attention (R10 structure, BN=64) ----------
// SMEM: Qhi 64K | Qlo 64K | KV hi 32K + lo 32K = 192K
#define SM_QH 0
#define SM_QL 65536
#define SM_KH 131072
#define ATTN_SMEM (131072 + 65536)

__global__ __launch_bounds__(256, 1) void attn_mma_kernel(
    const unsigned short* __restrict__ QH, const unsigned short* __restrict__ QL,
    const unsigned short* __restrict__ KH, const unsigned short* __restrict__ KL,
    const unsigned short* __restrict__ VH, const unsigned short* __restrict__ VL,
    unsigned short* __restrict__ OH, unsigned short* __restrict__ OL)
{
    extern __shared__ char smc[];
    const uint32_t sb = smem_u32(smc);
    const int tid = threadIdx.x, lane = tid & 31, w = tid >> 5;
    const int b = blockIdx.y, m0 = blockIdx.x * 128;

    // Q hi/lo -> swizzled smem via cp.async (group 0)
    {
        const unsigned short* QHb = QH + ((size_t)b * HW_ + m0) * C_;
        const unsigned short* QLb = QL + ((size_t)b * HW_ + m0) * C_;
        for (int u = tid; u < 4096; u += 256) {
            int row = u >> 5, cc = u & 31;
            uint32_t sw = (uint32_t)(row * 512 + ((cc ^ (row & 7)) << 4));
            cpa16(sb + SM_QH + sw, QHb + (size_t)row * C_ + cc * 8);
            cpa16(sb + SM_QL + sw, QLb + (size_t)row * C_ + cc * 8);
        }
        CP_COMMIT();
    }

    const int t8 = lane & 7, gq = lane >> 3;
    const int arow  = (w << 4) + ((gq & 1) << 3) + t8;
    const uint32_t aoff = sb + SM_QH + arow * 512;
    const int arow7 = arow & 7, akh = gq >> 1;
    const int brow_l = ((gq >> 1) << 3) + t8, bkh = gq & 1;
    const int vrow_l = ((gq & 1) << 3) + t8, vnh = gq >> 1;

    float oacc[128];
#pragma unroll
    for (int i = 0; i < 128; ++i) oacc[i] = 0.f;
    float l0 = 0.f, l1 = 0.f;

    const unsigned short* KHb = KH + (size_t)b * HW_ * C_;
    const unsigned short* KLb = KL + (size_t)b * HW_ * C_;
    const unsigned short* VHb = VH + (size_t)b * HW_ * C_;
    const unsigned short* VLb = VL + (size_t)b * HW_ * C_;

    for (int kt = 0; kt < 64; ++kt) {
        __syncthreads();                       // prev V readers done
        {   // K tile 64x256 hi/lo -> smem
            size_t base = (size_t)kt * 64 * C_;
#pragma unroll
            for (int rq = 0; rq < 8; ++rq) {
                int u = tid + rq * 256;
                int row = u >> 5, cc = u & 31;
                uint32_t sw = (uint32_t)(row * 512 + ((cc ^ (row & 7)) << 4));
                cpa16(sb + SM_KH + sw,          KHb + base + row * C_ + cc * 8);
                cpa16(sb + SM_KH + 32768u + sw, KLb + base + row * C_ + cc * 8);
            }
            CP_COMMIT(); CP_WAIT0();           // also retires Q on iter 0
        }
        __syncthreads();

        // ---- S = Q K^T ----
        float sacc[32];
#pragma unroll
        for (int i = 0; i < 32; ++i) sacc[i] = 0.f;
#pragma unroll 2
        for (int kk = 0; kk < 16; ++kk) {
            uint32_t ah[4], al[4];
            uint32_t ad = aoff + (uint32_t)(((2*kk + akh) ^ arow7) << 4);
            LDSM4(ah, ad);
            LDSM4(al, ad + 65536u);
#pragma unroll
            for (int np = 0; np < 4; ++np) {
                int brow = np * 16 + brow_l;
                uint32_t bd = sb + SM_KH +
                    (uint32_t)(brow * 512 + (((2*kk + bkh) ^ (brow & 7)) << 4));
                uint32_t bh[4], bl[4];
                LDSM4(bh, bd);
                LDSM4(bl, bd + 32768u);
                mma16816(&sacc[(2*np)*4],   ah, bh[0], bh[1]);
                mma16816(&sacc[(2*np)*4],   ah, bl[0], bl[1]);
                mma16816(&sacc[(2*np)*4],   al, bh[0], bh[1]);
                mma16816(&sacc[(2*np+1)*4], ah, bh[2], bh[3]);
                mma16816(&sacc[(2*np+1)*4], ah, bl[2], bl[3]);
                mma16816(&sacc[(2*np+1)*4], al, bh[2], bh[3]);
            }
        }

        __syncthreads();                       // all warps done reading K
        {   // V tile -> same buffer, overlapped with softmax
            size_t base = (size_t)kt * 64 * C_;
#pragma unroll
            for (int rq = 0; rq < 8; ++rq) {
                int u = tid + rq * 256;
                int row = u >> 5, cc = u & 31;
                uint32_t sw = (uint32_t)(row * 512 + ((cc ^ (row & 7)) << 4));
                cpa16(sb + SM_KH + sw,          VHb + base + row * C_ + cc * 8);
                cpa16(sb + SM_KH + 32768u + sw, VLb + base + row * C_ + cc * 8);
            }
            CP_COMMIT();
        }

        // ---- softmax (bounded logits: no max-sub; 1/16 folded here) ----
        uint32_t ph[4][4], pl[4][4];
#pragma unroll
        for (int j = 0; j < 4; ++j) {
            float e[8];
#pragma unroll
            for (int i = 0; i < 4; ++i) {
                e[i]   = __expf(sacc[(2*j)*4 + i]   * 0.0625f);
                e[4+i] = __expf(sacc[(2*j+1)*4 + i] * 0.0625f);
            }
            l0 += e[0] + e[1] + e[4] + e[5];
            l1 += e[2] + e[3] + e[6] + e[7];
            ph[j][0] = packhi(e[0], e[1]); pl[j][0] = packlo(e[0], e[1]);
            ph[j][1] = packhi(e[2], e[3]); pl[j][1] = packlo(e[2], e[3]);
            ph[j][2] = packhi(e[4], e[5]); pl[j][2] = packlo(e[4], e[5]);
            ph[j][3] = packhi(e[6], e[7]); pl[j][3] = packlo(e[6], e[7]);
        }

        CP_WAIT0();
        __syncthreads();

        // ---- O += P V ----
#pragma unroll
        for (int j = 0; j < 4; ++j) {
            int vrow = j * 16 + vrow_l;
            uint32_t vbase = sb + SM_KH + (uint32_t)(vrow * 512);
            int vrow7 = vrow & 7;
#pragma unroll
            for (int p = 0; p < 16; ++p) {
                uint32_t vd = vbase + (uint32_t)(((2*p + vnh) ^ vrow7) << 4);
                uint32_t bh[4], bl[4];
                LDSM4T(bh, vd);
                LDSM4T(bl, vd + 32768u);
                mma16816(&oacc[(2*p)*4],   ph[j], bh[0], bh[1]);
                mma16816(&oacc[(2*p)*4],   ph[j], bl[0], bl[1]);
                mma16816(&oacc[(2*p)*4],   pl[j], bh[0], bh[1]);
                mma16816(&oacc[(2*p+1)*4], ph[j], bh[2], bh[3]);
                mma16816(&oacc[(2*p+1)*4], ph[j], bl[2], bl[3]);
                mma16816(&oacc[(2*p+1)*4], pl[j], bh[2], bh[3]);
            }
        }
    }

    // ---- epilogue: O /= l, store as bf16 hi/lo split ----
    l0 += __shfl_xor_sync(0xffffffffu, l0, 1);
    l0 += __shfl_xor_sync(0xffffffffu, l0, 2);
    l1 += __shfl_xor_sync(0xffffffffu, l1, 1);
    l1 += __shfl_xor_sync(0xffffffffu, l1, 2);
    float i0 = 1.f / l0, i1 = 1.f / l1;
    int r = lane >> 2, cq = (lane & 3) * 2;
    size_t ob = ((size_t)b * HW_ + m0 + w * 16) * C_;
#pragma unroll
    for (int nn = 0; nn < 32; ++nn) {
        float a0 = oacc[nn*4]   * i0, a1 = oacc[nn*4+1] * i0;
        float b0 = oacc[nn*4+2] * i1, b1 = oacc[nn*4+3] * i1;
        size_t p0 = ob + (size_t)r * C_ + nn * 8 + cq;
        size_t p1 = ob + (size_t)(r + 8) * C_ + nn * 8 + cq;
        *(uint32_t*)(OH + p0) = packhi(a0, a1);
        *(uint32_t*)(OL + p0) = packlo(a0, a1);
        *(uint32_t*)(OH + p1) = packhi(b0, b1);
        *(uint32_t*)(OL + p1) = packlo(b0, b1);
    }
}

// ---------------- launch ----------------
extern "C" void kernel_launch(void* const* d_in, const int* in_sizes, int n_in,
                              void* d_out, int out_size)
{
    const float* x   = (const float*)d_in[0];
    const float* gam = (const float*)d_in[1];
    const float* bet = (const float*)d_in[2];
    const float* wq  = (const float*)d_in[3];
    const float* bq  = (const float*)d_in[4];
    const float* wk  = (const float*)d_in[5];
    const float* bk  = (const float*)d_in[6];
    const float* wv  = (const float*)d_in[7];
    const float* bv  = (const float*)d_in[8];
    const float* wo  = (const float*)d_in[9];
    const float* bo  = (const float*)d_in[10];
    float* out = (float*)d_out;

    unsigned short *hh, *hl, *qh, *ql, *kh, *kl, *vh, *vl, *aoh, *aol, *wsh, *wsl;
    cudaGetSymbolAddress((void**)&hh,  g_hh);
    cudaGetSymbolAddress((void**)&hl,  g_hl);
    cudaGetSymbolAddress((void**)&qh,  g_qh);
    cudaGetSymbolAddress((void**)&ql,  g_ql);
    cudaGetSymbolAddress((void**)&kh,  g_kh);
    cudaGetSymbolAddress((void**)&kl,  g_kl);
    cudaGetSymbolAddress((void**)&vh,  g_vh);
    cudaGetSymbolAddress((void**)&vl,  g_vl);
    cudaGetSymbolAddress((void**)&aoh, g_aoh);
    cudaGetSymbolAddress((void**)&aol, g_aol);
    cudaGetSymbolAddress((void**)&wsh, g_wh);
    cudaGetSymbolAddress((void**)&wsl, g_wl);

    cudaFuncSetAttribute(attn_mma_kernel,
                         cudaFuncAttributeMaxDynamicSharedMemorySize, ATTN_SMEM);

    ln_kernel<<<NT_ / 8, 256>>>(x, gam, bet, hh, hl);

    const int WG = (C_ * C_) / (256 * 4);   // 64 blocks per weight
    cvt_split_kernel<<<WG, 256>>>(wq, wsh + 0*C_*C_, wsl + 0*C_*C_);
    cvt_split_kernel<<<WG, 256>>>(wk, wsh + 1*C_*C_, wsl + 1*C_*C_);
    cvt_split_kernel<<<WG, 256>>>(wv, wsh + 2*C_*C_, wsl + 2*C_*C_);
    cvt_split_kernel<<<WG, 256>>>(wo, wsh + 3*C_*C_, wsl + 3*C_*C_);

    dim3 gg(C_ / 128, NT_ / 128);   // (2, 256)
    gemm2_kernel<<<gg, 256>>>(hh, hl, wsh + 0*C_*C_, wsl + 0*C_*C_, bq, nullptr,
                              nullptr, qh, ql);
    gemm2_kernel<<<gg, 256>>>(hh, hl, wsh + 1*C_*C_, wsl + 1*C_*C_, bk, nullptr,
                              nullptr, kh, kl);
    gemm2_kernel<<<gg, 256>>>(hh, hl, wsh + 2*C_*C_, wsl + 2*C_*C_, bv, nullptr,
                              nullptr, vh, vl);

    attn_mma_kernel<<<dim3(HW_ / 128, B_), 256, ATTN_SMEM>>>(qh, ql, kh, kl, vh, vl, aoh, aol);

    gemm2_kernel<<<gg, 256>>>(aoh, aol, wsh + 3*C_*C_, wsl + 3*C_*C_, bo, x,
                              out, nullptr, nullptr);
}

// round 16
// speedup vs baseline: 1.0022x; 1.0012x over previous
#include <cuda_runtime.h>
#include <cuda_bf16.h>
#include <math.h>
#include <stdint.h>

#define B_   8
#define HW_  4096
#define C_   256
#define NT_  (B_ * HW_)

static __device__ unsigned short g_hh[(size_t)NT_ * C_];
static __device__ unsigned short g_hl[(size_t)NT_ * C_];
static __device__ unsigned short g_qh[(size_t)NT_ * C_];
static __device__ unsigned short g_ql[(size_t)NT_ * C_];
static __device__ unsigned short g_kh[(size_t)NT_ * C_];
static __device__ unsigned short g_kl[(size_t)NT_ * C_];
static __device__ unsigned short g_vh[(size_t)NT_ * C_];
static __device__ unsigned short g_vl[(size_t)NT_ * C_];
static __device__ unsigned short g_aoh[(size_t)NT_ * C_];
static __device__ unsigned short g_aol[(size_t)NT_ * C_];
static __device__ unsigned short g_wh[4][C_ * C_];
static __device__ unsigned short g_wl[4][C_ * C_];

// ---------------- helpers (sm_80-level PTX only) ----------------
__device__ __forceinline__ uint32_t smem_u32(const void* p) {
    uint32_t a;
    asm("{ .reg .u64 t; cvta.to.shared.u64 t, %1; cvt.u32.u64 %0, t; }" : "=r"(a) : "l"(p));
    return a;
}
__device__ __forceinline__ void cpa16(uint32_t s, const void* g) {
    asm volatile("cp.async.cg.shared.global [%0], [%1], 16;" :: "r"(s), "l"(g));
}
#define CP_COMMIT() asm volatile("cp.async.commit_group;" ::: "memory")
#define CP_WAIT0()  asm volatile("cp.async.wait_group 0;" ::: "memory")
#define CP_WAIT1()  asm volatile("cp.async.wait_group 1;" ::: "memory")
#define LDSM4(R, A) \
    asm volatile("ldmatrix.sync.aligned.m8n8.x4.shared.b16 {%0,%1,%2,%3}, [%4];" \
        : "=r"((R)[0]), "=r"((R)[1]), "=r"((R)[2]), "=r"((R)[3]) : "r"(A))
#define LDSM4T(R, A) \
    asm volatile("ldmatrix.sync.aligned.m8n8.x4.trans.shared.b16 {%0,%1,%2,%3}, [%4];" \
        : "=r"((R)[0]), "=r"((R)[1]), "=r"((R)[2]), "=r"((R)[3]) : "r"(A))
__device__ __forceinline__ void mma16816(float* c, const uint32_t* a, uint32_t b0, uint32_t b1) {
    asm volatile("mma.sync.aligned.m16n8k16.row.col.f32.bf16.bf16.f32 "
                 "{%0,%1,%2,%3}, {%4,%5,%6,%7}, {%8,%9}, {%0,%1,%2,%3};"
                 : "+f"(c[0]), "+f"(c[1]), "+f"(c[2]), "+f"(c[3])
                 : "r"(a[0]), "r"(a[1]), "r"(a[2]), "r"(a[3]), "r"(b0), "r"(b1));
}
__device__ __forceinline__ uint32_t pack2(__nv_bfloat16 a, __nv_bfloat16 b) {
    __nv_bfloat162 t; t.x = a; t.y = b;
    return *reinterpret_cast<uint32_t*>(&t);
}
__device__ __forceinline__ void split2(float f, __nv_bfloat16& h, __nv_bfloat16& l) {
    h = __float2bfloat16(f);
    l = __float2bfloat16(f - __bfloat162float(h));
}
__device__ __forceinline__ uint32_t packhi(float a, float b) {
    return pack2(__float2bfloat16(a), __float2bfloat16(b));
}
__device__ __forceinline__ uint32_t packlo(float a, float b) {
    __nv_bfloat16 ha = __float2bfloat16(a), hb = __float2bfloat16(b);
    return pack2(__float2bfloat16(a - __bfloat162float(ha)),
                 __float2bfloat16(b - __bfloat162float(hb)));
}

// ---------------- LayerNorm -> bf16 hi/lo ----------------
__global__ __launch_bounds__(256) void ln_kernel(
    const float* __restrict__ x, const float* __restrict__ gamma,
    const float* __restrict__ beta,
    unsigned short* __restrict__ hh, unsigned short* __restrict__ hl)
{
    int token = blockIdx.x * 8 + (threadIdx.x >> 5);
    int lane  = threadIdx.x & 31;
    const float4* xr = (const float4*)(x + (size_t)token * C_);
    float4 a = xr[lane];
    float4 b = xr[lane + 32];
    float s  = a.x + a.y + a.z + a.w + b.x + b.y + b.z + b.w;
    float s2 = a.x*a.x + a.y*a.y + a.z*a.z + a.w*a.w
             + b.x*b.x + b.y*b.y + b.z*b.z + b.w*b.w;
#pragma unroll
    for (int o = 16; o; o >>= 1) {
        s  += __shfl_xor_sync(0xffffffffu, s,  o);
        s2 += __shfl_xor_sync(0xffffffffu, s2, o);
    }
    float mu   = s * (1.0f / C_);
    float rstd = rsqrtf(s2 * (1.0f / C_) - mu * mu + 1e-5f);
    float4 g0 = ((const float4*)gamma)[lane], g1 = ((const float4*)gamma)[lane + 32];
    float4 e0 = ((const float4*)beta)[lane],  e1 = ((const float4*)beta)[lane + 32];
    float o0[4], o1[4];
    o0[0] = (a.x-mu)*rstd*g0.x + e0.x; o0[1] = (a.y-mu)*rstd*g0.y + e0.y;
    o0[2] = (a.z-mu)*rstd*g0.z + e0.z; o0[3] = (a.w-mu)*rstd*g0.w + e0.w;
    o1[0] = (b.x-mu)*rstd*g1.x + e1.x; o1[1] = (b.y-mu)*rstd*g1.y + e1.y;
    o1[2] = (b.z-mu)*rstd*g1.z + e1.z; o1[3] = (b.w-mu)*rstd*g1.w + e1.w;
    uint2 h0, l0, h1, l1;
    h0.x = packhi(o0[0],o0[1]); h0.y = packhi(o0[2],o0[3]);
    l0.x = packlo(o0[0],o0[1]); l0.y = packlo(o0[2],o0[3]);
    h1.x = packhi(o1[0],o1[1]); h1.y = packhi(o1[2],o1[3]);
    l1.x = packlo(o1[0],o1[1]); l1.y = packlo(o1[2],o1[3]);
    ((uint2*)(hh + (size_t)token * C_))[lane]      = h0;
    ((uint2*)(hh + (size_t)token * C_))[lane + 32] = h1;
    ((uint2*)(hl + (size_t)token * C_))[lane]      = l0;
    ((uint2*)(hl + (size_t)token * C_))[lane + 32] = l1;
}

// ---------------- fp32 -> bf16 hi/lo split (weights) ----------------
__global__ __launch_bounds__(256) void cvt_split_kernel(
    const float* __restrict__ in, unsigned short* __restrict__ hi,
    unsigned short* __restrict__ lo)
{
    size_t i = ((size_t)blockIdx.x * 256 + threadIdx.x) * 4;
    float4 v = *(const float4*)(in + i);
    uint2 hv, lv;
    hv.x = packhi(v.x, v.y); hv.y = packhi(v.z, v.w);
    lv.x = packlo(v.x, v.y); lv.y = packlo(v.z, v.w);
    *(uint2*)(hi + i) = hv;
    *(uint2*)(lo + i) = lv;
}

// ---------------- bf16-input double-buffered mma.sync GEMM ----------------
// out[M,256] = (Ahi+Alo)@(Whi+Wlo) 3-term + bias (+resid)
// Stage: AH@0(10240) AL@10240 WH@20480(8704) WL@29184 ; stride 37888; 2 stages.
#define G2_STG 37888

__device__ __forceinline__ void g2_fill(
    uint32_t d, const unsigned short* Ah, const unsigned short* Al,
    const unsigned short* Wh, const unsigned short* Wl,
    int m0, int n0, int k0, int tid)
{
#pragma unroll
    for (int r = 0; r < 2; ++r) {
        int c = tid + r * 256;
        int m = c >> 2, kq = c & 3;
        cpa16(d + m*80 + kq*16,          Ah + (size_t)(m0+m)*C_ + k0 + kq*8);
        cpa16(d + 10240u + m*80 + kq*16, Al + (size_t)(m0+m)*C_ + k0 + kq*8);
    }
#pragma unroll
    for (int r = 0; r < 2; ++r) {
        int c = tid + r * 256;
        int k = c >> 4, nq = c & 15;
        cpa16(d + 20480u + k*272 + nq*16, Wh + (size_t)(k0+k)*C_ + n0 + nq*8);
        cpa16(d + 29184u + k*272 + nq*16, Wl + (size_t)(k0+k)*C_ + n0 + nq*8);
    }
}

__global__ __launch_bounds__(256) void gemm2_kernel(
    const unsigned short* __restrict__ Ah, const unsigned short* __restrict__ Al,
    const unsigned short* __restrict__ Wh, const unsigned short* __restrict__ Wl,
    const float* __restrict__ bias, const float* __restrict__ resid,
    float* __restrict__ outf,
    unsigned short* __restrict__ ohi, unsigned short* __restrict__ olo)
{
    __shared__ char gsm[2 * G2_STG];
    const uint32_t sb = smem_u32(gsm);
    const int tid = threadIdx.x, lane = tid & 31, w = tid >> 5;
    const int wm = w & 3, wn = w >> 2;
    const int m0 = blockIdx.y * 128, n0 = blockIdx.x * 128;
    const int t8 = lane & 7, gq = lane >> 3;

    float acc[2][8][4];
#pragma unroll
    for (int i = 0; i < 2; ++i)
#pragma unroll
        for (int j = 0; j < 8; ++j)
#pragma unroll
            for (int q = 0; q < 4; ++q) acc[i][j][q] = 0.f;

    g2_fill(sb,          Ah, Al, Wh, Wl, m0, n0, 0,  tid); CP_COMMIT();
    g2_fill(sb + G2_STG, Ah, Al, Wh, Wl, m0, n0, 32, tid); CP_COMMIT();

    for (int s = 0; s < 8; ++s) {
        if (s < 7) { CP_WAIT1(); } else { CP_WAIT0(); }
        __syncthreads();
        const uint32_t base = sb + (uint32_t)((s & 1) * G2_STG);
#pragma unroll
        for (int kk = 0; kk < 2; ++kk) {
            uint32_t ah[2][4], al[2][4];
#pragma unroll
            for (int mt = 0; mt < 2; ++mt) {
                int row = wm*32 + mt*16 + ((gq&1)<<3) + t8;
                uint32_t ad = base + row*80 + kk*32 + (gq>>1)*16;
                LDSM4(ah[mt], ad);
                LDSM4(al[mt], ad + 10240u);
            }
            int rowk = kk*16 + ((gq&1)<<3) + t8;
#pragma unroll
            for (int j = 0; j < 4; ++j) {
                uint32_t bd = base + 20480u + rowk*272 + wn*128 + (2*j + (gq>>1))*16;
                uint32_t bh[4], bl[4];
                LDSM4T(bh, bd);
                LDSM4T(bl, bd + 8704u);
#pragma unroll
                for (int mt = 0; mt < 2; ++mt) {
                    mma16816(acc[mt][2*j],   ah[mt], bh[0], bh[1]);
                    mma16816(acc[mt][2*j],   ah[mt], bl[0], bl[1]);
                    mma16816(acc[mt][2*j],   al[mt], bh[0], bh[1]);
                    mma16816(acc[mt][2*j+1], ah[mt], bh[2], bh[3]);
                    mma16816(acc[mt][2*j+1], ah[mt], bl[2], bl[3]);
                    mma16816(acc[mt][2*j+1], al[mt], bh[2], bh[3]);
                }
            }
        }
        __syncthreads();
        if (s < 6) {
            g2_fill(sb + (uint32_t)((s & 1) * G2_STG),
                    Ah, Al, Wh, Wl, m0, n0, (s + 2) * 32, tid);
            CP_COMMIT();
        }
    }

#pragma unroll
    for (int mt = 0; mt < 2; ++mt)
#pragma unroll
        for (int n8 = 0; n8 < 8; ++n8) {
            int row = m0 + wm*32 + mt*16 + (lane >> 2);
            int col = n0 + wn*64 + n8*8 + (lane & 3)*2;
            size_t o0 = (size_t)row * C_ + col, o1 = o0 + 8 * C_;
            float b0 = bias[col], b1 = bias[col + 1];
            float v00 = acc[mt][n8][0] + b0, v01 = acc[mt][n8][1] + b1;
            float v10 = acc[mt][n8][2] + b0, v11 = acc[mt][n8][3] + b1;
            if (resid) {
                v00 += resid[o0]; v01 += resid[o0 + 1];
                v10 += resid[o1]; v11 += resid[o1 + 1];
            }
            if (outf) {
                *(float2*)(outf + o0) = make_float2(v00, v01);
                *(float2*)(outf + o1) = make_float2(v10, v11);
            }
            if (ohi) {
                *(uint32_t*)(ohi + o0) = packhi(v00, v01);
                *(uint32_t*)(olo + o0) = packlo(v00, v01);
                *(uint32_t*)(ohi + o1) = packhi(v10, v11);
                *(uint32_t*)(olo + o1) = packlo(v10, v11);
            }
        }
}

// ---------------- mma.sync flash attention (R10 structure, BN=64) ----------
// SMEM: Qhi 64K | Qlo 64K | KV hi 32K + lo 32K = 192K
#define SM_QH 0
#define SM_QL 65536
#define SM_KH 131072
#define ATTN_SMEM (131072 + 65536)

__global__ __launch_bounds__(256, 1) void attn_mma_kernel(
    const unsigned short* __restrict__ QH, const unsigned short* __restrict__ QL,
    const unsigned short* __restrict__ KH, const unsigned short* __restrict__ KL,
    const unsigned short* __restrict__ VH, const unsigned short* __restrict__ VL,
    unsigned short* __restrict__ OH, unsigned short* __restrict__ OL)
{
    extern __shared__ char smc[];
    const uint32_t sb = smem_u32(smc);
    const int tid = threadIdx.x, lane = tid & 31, w = tid >> 5;
    const int b = blockIdx.y, m0 = blockIdx.x * 128;

    // Q hi/lo -> swizzled smem via cp.async (group 0)
    {
        const unsigned short* QHb = QH + ((size_t)b * HW_ + m0) * C_;
        const unsigned short* QLb = QL + ((size_t)b * HW_ + m0) * C_;
        for (int u = tid; u < 4096; u += 256) {
            int row = u >> 5, cc = u & 31;
            uint32_t sw = (uint32_t)(row * 512 + ((cc ^ (row & 7)) << 4));
            cpa16(sb + SM_QH + sw, QHb + (size_t)row * C_ + cc * 8);
            cpa16(sb + SM_QL + sw, QLb + (size_t)row * C_ + cc * 8);
        }
        CP_COMMIT();
    }

    const int t8 = lane & 7, gq = lane >> 3;
    const int arow  = (w << 4) + ((gq & 1) << 3) + t8;
    const uint32_t aoff = sb + SM_QH + arow * 512;
    const int arow7 = arow & 7, akh = gq >> 1;
    const int brow_l = ((gq >> 1) << 3) + t8, bkh = gq & 1;
    const int vrow_l = ((gq & 1) << 3) + t8, vnh = gq >> 1;

    float oacc[128];
#pragma unroll
    for (int i = 0; i < 128; ++i) oacc[i] = 0.f;
    float l0 = 0.f, l1 = 0.f;

    const unsigned short* KHb = KH + (size_t)b * HW_ * C_;
    const unsigned short* KLb = KL + (size_t)b * HW_ * C_;
    const unsigned short* VHb = VH + (size_t)b * HW_ * C_;
    const unsigned short* VLb = VL + (size_t)b * HW_ * C_;

    for (int kt = 0; kt < 64; ++kt) {
        __syncthreads();                       // prev V readers done
        {   // K tile 64x256 hi/lo -> smem
            size_t base = (size_t)kt * 64 * C_;
#pragma unroll
            for (int rq = 0; rq < 8; ++rq) {
                int u = tid + rq * 256;
                int row = u >> 5, cc = u & 31;
                uint32_t sw = (uint32_t)(row * 512 + ((cc ^ (row & 7)) << 4));
                cpa16(sb + SM_KH + sw,          KHb + base + row * C_ + cc * 8);
                cpa16(sb + SM_KH + 32768u + sw, KLb + base + row * C_ + cc * 8);
            }
            CP_COMMIT(); CP_WAIT0();           // also retires Q on iter 0
        }
        __syncthreads();

        // ---- S = Q K^T ----
        float sacc[32];
#pragma unroll
        for (int i = 0; i < 32; ++i) sacc[i] = 0.f;
#pragma unroll 2
        for (int kk = 0; kk < 16; ++kk) {
            uint32_t ah[4], al[4];
            uint32_t ad = aoff + (uint32_t)(((2*kk + akh) ^ arow7) << 4);
            LDSM4(ah, ad);
            LDSM4(al, ad + 65536u);
#pragma unroll
            for (int np = 0; np < 4; ++np) {
                int brow = np * 16 + brow_l;
                uint32_t bd = sb + SM_KH +
                    (uint32_t)(brow * 512 + (((2*kk + bkh) ^ (brow & 7)) << 4));
                uint32_t bh[4], bl[4];
                LDSM4(bh, bd);
                LDSM4(bl, bd + 32768u);
                mma16816(&sacc[(2*np)*4],   ah, bh[0], bh[1]);
                mma16816(&sacc[(2*np)*4],   ah, bl[0], bl[1]);
                mma16816(&sacc[(2*np)*4],   al, bh[0], bh[1]);
                mma16816(&sacc[(2*np+1)*4], ah, bh[2], bh[3]);
                mma16816(&sacc[(2*np+1)*4], ah, bl[2], bl[3]);
                mma16816(&sacc[(2*np+1)*4], al, bh[2], bh[3]);
            }
        }

        __syncthreads();                       // all warps done reading K
        {   // V tile -> same buffer, overlapped with softmax
            size_t base = (size_t)kt * 64 * C_;
#pragma unroll
            for (int rq = 0; rq < 8; ++rq) {
                int u = tid + rq * 256;
                int row = u >> 5, cc = u & 31;
                uint32_t sw = (uint32_t)(row * 512 + ((cc ^ (row & 7)) << 4));
                cpa16(sb + SM_KH + sw,          VHb + base + row * C_ + cc * 8);
                cpa16(sb + SM_KH + 32768u + sw, VLb + base + row * C_ + cc * 8);
            }
            CP_COMMIT();
        }

        // ---- softmax (bounded logits: no max-sub; 1/16 folded here) ----
        uint32_t ph[4][4], pl[4][4];
#pragma unroll
        for (int j = 0; j < 4; ++j) {
            float e[8];
#pragma unroll
            for (int i = 0; i < 4; ++i) {
                e[i]   = __expf(sacc[(2*j)*4 + i]   * 0.0625f);
                e[4+i] = __expf(sacc[(2*j+1)*4 + i] * 0.0625f);
            }
            l0 += e[0] + e[1] + e[4] + e[5];
            l1 += e[2] + e[3] + e[6] + e[7];
            ph[j][0] = packhi(e[0], e[1]); pl[j][0] = packlo(e[0], e[1]);
            ph[j][1] = packhi(e[2], e[3]); pl[j][1] = packlo(e[2], e[3]);
            ph[j][2] = packhi(e[4], e[5]); pl[j][2] = packlo(e[4], e[5]);
            ph[j][3] = packhi(e[6], e[7]); pl[j][3] = packlo(e[6], e[7]);
        }

        CP_WAIT0();
        __syncthreads();

        // ---- O += P V ----
#pragma unroll
        for (int j = 0; j < 4; ++j) {
            int vrow = j * 16 + vrow_l;
            uint32_t vbase = sb + SM_KH + (uint32_t)(vrow * 512);
            int vrow7 = vrow & 7;
#pragma unroll
            for (int p = 0; p < 16; ++p) {
                uint32_t vd = vbase + (uint32_t)(((2*p + vnh) ^ vrow7) << 4);
                uint32_t bh[4], bl[4];
                LDSM4T(bh, vd);
                LDSM4T(bl, vd + 32768u);
                mma16816(&oacc[(2*p)*4],   ph[j], bh[0], bh[1]);
                mma16816(&oacc[(2*p)*4],   ph[j], bl[0], bl[1]);
                mma16816(&oacc[(2*p)*4],   pl[j], bh[0], bh[1]);
                mma16816(&oacc[(2*p+1)*4], ph[j], bh[2], bh[3]);
                mma16816(&oacc[(2*p+1)*4], ph[j], bl[2], bl[3]);
                mma16816(&oacc[(2*p+1)*4], pl[j], bh[2], bh[3]);
            }
        }
    }

    // ---- epilogue: O /= l, store as bf16 hi/lo split ----
    l0 += __shfl_xor_sync(0xffffffffu, l0, 1);
    l0 += __shfl_xor_sync(0xffffffffu, l0, 2);
    l1 += __shfl_xor_sync(0xffffffffu, l1, 1);
    l1 += __shfl_xor_sync(0xffffffffu, l1, 2);
    float i0 = 1.f / l0, i1 = 1.f / l1;
    int r = lane >> 2, cq = (lane & 3) * 2;
    size_t ob = ((size_t)b * HW_ + m0 + w * 16) * C_;
#pragma unroll
    for (int nn = 0; nn < 32; ++nn) {
        float a0 = oacc[nn*4]   * i0, a1 = oacc[nn*4+1] * i0;
        float b0 = oacc[nn*4+2] * i1, b1 = oacc[nn*4+3] * i1;
        size_t p0 = ob + (size_t)r * C_ + nn * 8 + cq;
        size_t p1 = ob + (size_t)(r + 8) * C_ + nn * 8 + cq;
        *(uint32_t*)(OH + p0) = packhi(a0, a1);
        *(uint32_t*)(OL + p0) = packlo(a0, a1);
        *(uint32_t*)(OH + p1) = packhi(b0, b1);
        *(uint32_t*)(OL + p1) = packlo(b0, b1);
    }
}

// ---------------- launch ----------------
extern "C" void kernel_launch(void* const* d_in, const int* in_sizes, int n_in,
                              void* d_out, int out_size)
{
    const float* x   = (const float*)d_in[0];
    const float* gam = (const float*)d_in[1];
    const float* bet = (const float*)d_in[2];
    const float* wq  = (const float*)d_in[3];
    const float* bq  = (const float*)d_in[4];
    const float* wk  = (const float*)d_in[5];
    const float* bk  = (const float*)d_in[6];
    const float* wv  = (const float*)d_in[7];
    const float* bv  = (const float*)d_in[8];
    const float* wo  = (const float*)d_in[9];
    const float* bo  = (const float*)d_in[10];
    float* out = (float*)d_out;

    unsigned short *hh, *hl, *qh, *ql, *kh, *kl, *vh, *vl, *aoh, *aol, *wsh, *wsl;
    cudaGetSymbolAddress((void**)&hh,  g_hh);
    cudaGetSymbolAddress((void**)&hl,  g_hl);
    cudaGetSymbolAddress((void**)&qh,  g_qh);
    cudaGetSymbolAddress((void**)&ql,  g_ql);
    cudaGetSymbolAddress((void**)&kh,  g_kh);
    cudaGetSymbolAddress((void**)&kl,  g_kl);
    cudaGetSymbolAddress((void**)&vh,  g_vh);
    cudaGetSymbolAddress((void**)&vl,  g_vl);
    cudaGetSymbolAddress((void**)&aoh, g_aoh);
    cudaGetSymbolAddress((void**)&aol, g_aol);
    cudaGetSymbolAddress((void**)&wsh, g_wh);
    cudaGetSymbolAddress((void**)&wsl, g_wl);

    cudaFuncSetAttribute(attn_mma_kernel,
                         cudaFuncAttributeMaxDynamicSharedMemorySize, ATTN_SMEM);

    ln_kernel<<<NT_ / 8, 256>>>(x, gam, bet, hh, hl);

    const int WG = (C_ * C_) / (256 * 4);   // 64 blocks per weight
    cvt_split_kernel<<<WG, 256>>>(wq, wsh + 0*C_*C_, wsl + 0*C_*C_);
    cvt_split_kernel<<<WG, 256>>>(wk, wsh + 1*C_*C_, wsl + 1*C_*C_);
    cvt_split_kernel<<<WG, 256>>>(wv, wsh + 2*C_*C_, wsl + 2*C_*C_);
    cvt_split_kernel<<<WG, 256>>>(wo, wsh + 3*C_*C_, wsl + 3*C_*C_);

    dim3 gg(C_ / 128, NT_ / 128);   // (2, 256)
    gemm2_kernel<<<gg, 256>>>(hh, hl, wsh + 0*C_*C_, wsl + 0*C_*C_, bq, nullptr,
                              nullptr, qh, ql);
    gemm2_kernel<<<gg, 256>>>(hh, hl, wsh + 1*C_*C_, wsl + 1*C_*C_, bk, nullptr,
                              nullptr, kh, kl);
    gemm2_kernel<<<gg, 256>>>(hh, hl, wsh + 2*C_*C_, wsl + 2*C_*C_, bv, nullptr,
                              nullptr, vh, vl);

    attn_mma_kernel<<<dim3(HW_ / 128, B_), 256, ATTN_SMEM>>>(qh, ql, kh, kl, vh, vl, aoh, aol);

    gemm2_kernel<<<gg, 256>>>(aoh, aol, wsh + 3*C_*C_, wsl + 3*C_*C_, bo, x,
                              out, nullptr, nullptr);
}